// round 1
// baseline (speedup 1.0000x reference)
#include <cuda_runtime.h>
#include <math.h>

#define B_SAMPLES 16384
#define EMB 64

__device__ __forceinline__ int lower_bound_i(const int* __restrict__ a, int n, int v) {
    int lo = 0, hi = n;
    while (lo < hi) {
        int m = (lo + hi) >> 1;
        if (a[m] < v) lo = m + 1; else hi = m;
    }
    return lo;
}

// Accumulate sum over rows [s, e) of table (row-major [*, 64] f32) into acc
// (each lane holds dims {2*lane, 2*lane+1}). Unrolled x4 for MLP.
__device__ __forceinline__ void segment_accum(
    const int* __restrict__ idx, int s, int e,
    const float* __restrict__ table, int lane,
    float& ax, float& ay)
{
    float a0x = 0.f, a0y = 0.f, a1x = 0.f, a1y = 0.f;
    float a2x = 0.f, a2y = 0.f, a3x = 0.f, a3y = 0.f;
    int i = s;
    for (; i + 4 <= e; i += 4) {
        int r0 = idx[i + 0];
        int r1 = idx[i + 1];
        int r2 = idx[i + 2];
        int r3 = idx[i + 3];
        float2 v0 = reinterpret_cast<const float2*>(table + (size_t)r0 * EMB)[lane];
        float2 v1 = reinterpret_cast<const float2*>(table + (size_t)r1 * EMB)[lane];
        float2 v2 = reinterpret_cast<const float2*>(table + (size_t)r2 * EMB)[lane];
        float2 v3 = reinterpret_cast<const float2*>(table + (size_t)r3 * EMB)[lane];
        a0x += v0.x; a0y += v0.y;
        a1x += v1.x; a1y += v1.y;
        a2x += v2.x; a2y += v2.y;
        a3x += v3.x; a3y += v3.y;
    }
    for (; i < e; i++) {
        int r = idx[i];
        float2 v = reinterpret_cast<const float2*>(table + (size_t)r * EMB)[lane];
        a0x += v.x; a0y += v.y;
    }
    ax += (a0x + a1x) + (a2x + a3x);
    ay += (a0y + a1y) + (a2y + a3y);
}

__global__ void __launch_bounds__(256) svdpp_kernel(
    const int* __restrict__ sci_ids,
    const int* __restrict__ pap_ids,
    const int* __restrict__ p_idx,
    const int* __restrict__ p_seg,
    const int* __restrict__ w_idx,
    const int* __restrict__ w_seg,
    const float* __restrict__ s_fact,
    const float* __restrict__ p_fact,
    const float* __restrict__ s_bias,
    const float* __restrict__ p_bias,
    const float* __restrict__ imp_fact,
    const float* __restrict__ imp_wish,
    const float* __restrict__ g_bias,
    float* __restrict__ out,
    int TP, int TW)
{
    int warp_id = (blockIdx.x * blockDim.x + threadIdx.x) >> 5;
    int lane = threadIdx.x & 31;
    if (warp_id >= B_SAMPLES) return;
    const int b = warp_id;

    // Segment boundaries (warp-uniform binary search; all lanes redundant,
    // loads broadcast within the warp).
    int ps = lower_bound_i(p_seg, TP, b);
    int pe = lower_bound_i(p_seg, TP, b + 1);
    int ws = lower_bound_i(w_seg, TW, b);
    int we = lower_bound_i(w_seg, TW, b + 1);

    // Pooled implicit sums, normalized by rsqrt(count) (0 if empty — sum is 0).
    float px = 0.f, py = 0.f;
    segment_accum(p_idx, ps, pe, imp_fact, lane, px, py);
    float pc = (float)(pe - ps);
    float pscale = rsqrtf(fmaxf(pc, 1.0f));
    px *= pscale; py *= pscale;

    float wx = 0.f, wy = 0.f;
    segment_accum(w_idx, ws, we, imp_wish, lane, wx, wy);
    float wc = (float)(we - ws);
    float wscale = rsqrtf(fmaxf(wc, 1.0f));
    wx *= wscale; wy *= wscale;

    const int sid = sci_ids[b];
    const int pid = pap_ids[b];

    float2 se = reinterpret_cast<const float2*>(s_fact + (size_t)sid * EMB)[lane];
    float2 pe2 = reinterpret_cast<const float2*>(p_fact + (size_t)pid * EMB)[lane];

    float partial = (se.x + px + wx) * pe2.x + (se.y + py + wy) * pe2.y;

    // Warp reduction over 64 dims (2 per lane).
    #pragma unroll
    for (int off = 16; off > 0; off >>= 1)
        partial += __shfl_xor_sync(0xFFFFFFFFu, partial, off);

    if (lane == 0) {
        out[b] = partial + s_bias[sid] + p_bias[pid] + g_bias[0];
    }
}

extern "C" void kernel_launch(void* const* d_in, const int* in_sizes, int n_in,
                              void* d_out, int out_size)
{
    const int*   sci_ids = (const int*)d_in[0];
    const int*   pap_ids = (const int*)d_in[1];
    const int*   p_idx   = (const int*)d_in[2];
    const int*   p_seg   = (const int*)d_in[3];
    const int*   w_idx   = (const int*)d_in[4];
    const int*   w_seg   = (const int*)d_in[5];
    const float* s_fact  = (const float*)d_in[6];
    const float* p_fact  = (const float*)d_in[7];
    const float* s_bias  = (const float*)d_in[8];
    const float* p_bias  = (const float*)d_in[9];
    const float* imp_f   = (const float*)d_in[10];
    const float* imp_w   = (const float*)d_in[11];
    const float* g_bias  = (const float*)d_in[12];
    float* out = (float*)d_out;

    const int TP = in_sizes[2];
    const int TW = in_sizes[4];

    // One warp per sample: 16384 warps / 8 warps per block = 2048 blocks.
    const int threads = 256;
    const int warps_per_block = threads / 32;
    const int blocks = (B_SAMPLES + warps_per_block - 1) / warps_per_block;

    svdpp_kernel<<<blocks, threads>>>(
        sci_ids, pap_ids, p_idx, p_seg, w_idx, w_seg,
        s_fact, p_fact, s_bias, p_bias, imp_f, imp_w, g_bias,
        out, TP, TW);
}

// round 2
// speedup vs baseline: 1.0582x; 1.0582x over previous
#include <cuda_runtime.h>
#include <math.h>

#define B_SAMPLES 16384
#define EMB 64

// Precomputed segment offsets (B+1 entries each). __device__ globals = legal scratch.
__device__ int g_p_off[B_SAMPLES + 1];
__device__ int g_w_off[B_SAMPLES + 1];

__device__ __forceinline__ int lower_bound_i(const int* __restrict__ a, int n, int v) {
    int lo = 0, hi = n;
    while (lo < hi) {
        int m = (lo + hi) >> 1;
        if (__ldg(a + m) < v) lo = m + 1; else hi = m;
    }
    return lo;
}

// One thread per segment id: compute lower bounds once, up front.
__global__ void __launch_bounds__(256) offsets_kernel(
    const int* __restrict__ p_seg, int TP,
    const int* __restrict__ w_seg, int TW)
{
    int t = blockIdx.x * blockDim.x + threadIdx.x;
    if (t > B_SAMPLES) return;
    g_p_off[t] = lower_bound_i(p_seg, TP, t);
    g_w_off[t] = lower_bound_i(w_seg, TW, t);
}

// Sum rows [s,e) of table ([*,64] f32); each lane owns dims {2*lane, 2*lane+1}.
// Unrolled x8: 8 independent 256B row loads in flight per warp.
__device__ __forceinline__ void segment_accum(
    const int* __restrict__ idx, int s, int e,
    const float* __restrict__ table, int lane,
    float& ax, float& ay)
{
    float sx[8], sy[8];
    #pragma unroll
    for (int k = 0; k < 8; k++) { sx[k] = 0.f; sy[k] = 0.f; }

    int i = s;
    for (; i + 8 <= e; i += 8) {
        int r[8];
        #pragma unroll
        for (int k = 0; k < 8; k++) r[k] = idx[i + k];
        float2 v[8];
        #pragma unroll
        for (int k = 0; k < 8; k++)
            v[k] = reinterpret_cast<const float2*>(table + (size_t)r[k] * EMB)[lane];
        #pragma unroll
        for (int k = 0; k < 8; k++) { sx[k] += v[k].x; sy[k] += v[k].y; }
    }
    for (; i < e; i++) {
        int r = idx[i];
        float2 v = reinterpret_cast<const float2*>(table + (size_t)r * EMB)[lane];
        sx[0] += v.x; sy[0] += v.y;
    }
    ax += ((sx[0] + sx[1]) + (sx[2] + sx[3])) + ((sx[4] + sx[5]) + (sx[6] + sx[7]));
    ay += ((sy[0] + sy[1]) + (sy[2] + sy[3])) + ((sy[4] + sy[5]) + (sy[6] + sy[7]));
}

__global__ void __launch_bounds__(256) svdpp_kernel(
    const int* __restrict__ sci_ids,
    const int* __restrict__ pap_ids,
    const int* __restrict__ p_idx,
    const int* __restrict__ w_idx,
    const float* __restrict__ s_fact,
    const float* __restrict__ p_fact,
    const float* __restrict__ s_bias,
    const float* __restrict__ p_bias,
    const float* __restrict__ imp_fact,
    const float* __restrict__ imp_wish,
    const float* __restrict__ g_bias,
    float* __restrict__ out)
{
    int warp_id = (blockIdx.x * blockDim.x + threadIdx.x) >> 5;
    int lane = threadIdx.x & 31;
    if (warp_id >= B_SAMPLES) return;
    const int b = warp_id;

    const int ps = g_p_off[b];
    const int pe = g_p_off[b + 1];
    const int ws = g_w_off[b];
    const int we = g_w_off[b + 1];

    // Kick off the per-sample row loads early (independent of the gathers).
    const int sid = sci_ids[b];
    const int pid = pap_ids[b];
    float2 se = reinterpret_cast<const float2*>(s_fact + (size_t)sid * EMB)[lane];
    float2 pv = reinterpret_cast<const float2*>(p_fact + (size_t)pid * EMB)[lane];

    float px = 0.f, py = 0.f;
    segment_accum(p_idx, ps, pe, imp_fact, lane, px, py);
    float pscale = rsqrtf(fmaxf((float)(pe - ps), 1.0f));
    px *= pscale; py *= pscale;

    float wx = 0.f, wy = 0.f;
    segment_accum(w_idx, ws, we, imp_wish, lane, wx, wy);
    float wscale = rsqrtf(fmaxf((float)(we - ws), 1.0f));
    wx *= wscale; wy *= wscale;

    float partial = (se.x + px + wx) * pv.x + (se.y + py + wy) * pv.y;

    #pragma unroll
    for (int off = 16; off > 0; off >>= 1)
        partial += __shfl_xor_sync(0xFFFFFFFFu, partial, off);

    if (lane == 0) {
        out[b] = partial + s_bias[sid] + p_bias[pid] + g_bias[0];
    }
}

extern "C" void kernel_launch(void* const* d_in, const int* in_sizes, int n_in,
                              void* d_out, int out_size)
{
    const int*   sci_ids = (const int*)d_in[0];
    const int*   pap_ids = (const int*)d_in[1];
    const int*   p_idx   = (const int*)d_in[2];
    const int*   p_seg   = (const int*)d_in[3];
    const int*   w_idx   = (const int*)d_in[4];
    const int*   w_seg   = (const int*)d_in[5];
    const float* s_fact  = (const float*)d_in[6];
    const float* p_fact  = (const float*)d_in[7];
    const float* s_bias  = (const float*)d_in[8];
    const float* p_bias  = (const float*)d_in[9];
    const float* imp_f   = (const float*)d_in[10];
    const float* imp_w   = (const float*)d_in[11];
    const float* g_bias  = (const float*)d_in[12];
    float* out = (float*)d_out;

    const int TP = in_sizes[2];
    const int TW = in_sizes[4];

    // Pass 1: segment offsets (16385 threads).
    offsets_kernel<<<(B_SAMPLES + 1 + 255) / 256, 256>>>(p_seg, TP, w_seg, TW);

    // Pass 2: one warp per sample.
    const int threads = 256;
    const int blocks = (B_SAMPLES * 32 + threads - 1) / threads;
    svdpp_kernel<<<blocks, threads>>>(
        sci_ids, pap_ids, p_idx, w_idx,
        s_fact, p_fact, s_bias, p_bias, imp_f, imp_w, g_bias, out);
}

// round 3
// speedup vs baseline: 1.0758x; 1.0166x over previous
#include <cuda_runtime.h>
#include <math.h>

#define B_SAMPLES 16384
#define EMB 64

// Precomputed segment offsets (B+1 entries each). __device__ globals = legal scratch.
__device__ int g_p_off[B_SAMPLES + 1];
__device__ int g_w_off[B_SAMPLES + 1];

__device__ __forceinline__ int lower_bound_i(const int* __restrict__ a, int n, int v) {
    int lo = 0, hi = n;
    while (lo < hi) {
        int m = (lo + hi) >> 1;
        if (__ldg(a + m) < v) lo = m + 1; else hi = m;
    }
    return lo;
}

// One thread per segment id: compute lower bounds once, up front.
__global__ void __launch_bounds__(256) offsets_kernel(
    const int* __restrict__ p_seg, int TP,
    const int* __restrict__ w_seg, int TW)
{
    int t = blockIdx.x * blockDim.x + threadIdx.x;
    if (t > B_SAMPLES) return;
    g_p_off[t] = lower_bound_i(p_seg, TP, t);
    g_w_off[t] = lower_bound_i(w_seg, TW, t);
}

// Sum rows [s,e) of table ([*,64] f32); each lane owns dims {2*lane, 2*lane+1}.
// Unrolled x8: 8 independent 256B row loads in flight per warp.
__device__ __forceinline__ void segment_accum(
    const int* __restrict__ idx, int s, int e,
    const float* __restrict__ table, int lane,
    float& ax, float& ay)
{
    float sx[8], sy[8];
    #pragma unroll
    for (int k = 0; k < 8; k++) { sx[k] = 0.f; sy[k] = 0.f; }

    int i = s;
    for (; i + 8 <= e; i += 8) {
        int r[8];
        #pragma unroll
        for (int k = 0; k < 8; k++) r[k] = idx[i + k];
        float2 v[8];
        #pragma unroll
        for (int k = 0; k < 8; k++)
            v[k] = reinterpret_cast<const float2*>(table + (size_t)r[k] * EMB)[lane];
        #pragma unroll
        for (int k = 0; k < 8; k++) { sx[k] += v[k].x; sy[k] += v[k].y; }
    }
    for (; i < e; i++) {
        int r = idx[i];
        float2 v = reinterpret_cast<const float2*>(table + (size_t)r * EMB)[lane];
        sx[0] += v.x; sy[0] += v.y;
    }
    ax += ((sx[0] + sx[1]) + (sx[2] + sx[3])) + ((sx[4] + sx[5]) + (sx[6] + sx[7]));
    ay += ((sy[0] + sy[1]) + (sy[2] + sy[3])) + ((sy[4] + sy[5]) + (sy[6] + sy[7]));
}

__global__ void __launch_bounds__(256) svdpp_kernel(
    const int* __restrict__ sci_ids,
    const int* __restrict__ pap_ids,
    const int* __restrict__ p_idx,
    const int* __restrict__ w_idx,
    const float* __restrict__ s_fact,
    const float* __restrict__ p_fact,
    const float* __restrict__ s_bias,
    const float* __restrict__ p_bias,
    const float* __restrict__ imp_fact,
    const float* __restrict__ imp_wish,
    const float* __restrict__ g_bias,
    float* __restrict__ out)
{
    int warp_id = (blockIdx.x * blockDim.x + threadIdx.x) >> 5;
    int lane = threadIdx.x & 31;
    if (warp_id >= B_SAMPLES) return;
    const int b = warp_id;

    const int ps = g_p_off[b];
    const int pe = g_p_off[b + 1];
    const int ws = g_w_off[b];
    const int we = g_w_off[b + 1];

    // Kick off the per-sample row loads early (independent of the gathers).
    const int sid = sci_ids[b];
    const int pid = pap_ids[b];
    float2 se = reinterpret_cast<const float2*>(s_fact + (size_t)sid * EMB)[lane];
    float2 pv = reinterpret_cast<const float2*>(p_fact + (size_t)pid * EMB)[lane];

    float px = 0.f, py = 0.f;
    segment_accum(p_idx, ps, pe, imp_fact, lane, px, py);
    float pscale = rsqrtf(fmaxf((float)(pe - ps), 1.0f));
    px *= pscale; py *= pscale;

    float wx = 0.f, wy = 0.f;
    segment_accum(w_idx, ws, we, imp_wish, lane, wx, wy);
    float wscale = rsqrtf(fmaxf((float)(we - ws), 1.0f));
    wx *= wscale; wy *= wscale;

    float partial = (se.x + px + wx) * pv.x + (se.y + py + wy) * pv.y;

    #pragma unroll
    for (int off = 16; off > 0; off >>= 1)
        partial += __shfl_xor_sync(0xFFFFFFFFu, partial, off);

    if (lane == 0) {
        out[b] = partial + s_bias[sid] + p_bias[pid] + g_bias[0];
    }
}

extern "C" void kernel_launch(void* const* d_in, const int* in_sizes, int n_in,
                              void* d_out, int out_size)
{
    const int*   sci_ids = (const int*)d_in[0];
    const int*   pap_ids = (const int*)d_in[1];
    const int*   p_idx   = (const int*)d_in[2];
    const int*   p_seg   = (const int*)d_in[3];
    const int*   w_idx   = (const int*)d_in[4];
    const int*   w_seg   = (const int*)d_in[5];
    const float* s_fact  = (const float*)d_in[6];
    const float* p_fact  = (const float*)d_in[7];
    const float* s_bias  = (const float*)d_in[8];
    const float* p_bias  = (const float*)d_in[9];
    const float* imp_f   = (const float*)d_in[10];
    const float* imp_w   = (const float*)d_in[11];
    const float* g_bias  = (const float*)d_in[12];
    float* out = (float*)d_out;

    const int TP = in_sizes[2];
    const int TW = in_sizes[4];

    // Pass 1: segment offsets (16385 threads).
    offsets_kernel<<<(B_SAMPLES + 1 + 255) / 256, 256>>>(p_seg, TP, w_seg, TW);

    // Pass 2: one warp per sample.
    const int threads = 256;
    const int blocks = (B_SAMPLES * 32 + threads - 1) / threads;
    svdpp_kernel<<<blocks, threads>>>(
        sci_ids, pap_ids, p_idx, w_idx,
        s_fact, p_fact, s_bias, p_bias, imp_f, imp_w, g_bias, out);
}